// round 4
// baseline (speedup 1.0000x reference)
#include <cuda_runtime.h>
#include <cstdint>

// Problem constants
#define BSZ 4096
#define DD  1024
#define CC  10000

// GEMM tiling
#define BM 128
#define BN 128
#define BK 16
#define PADF 4
#define BKP (BK + PADF)   // 20 floats row stride

// Scratch (device globals -- no allocation allowed)
__device__ float g_xx[BSZ];
__device__ float g_yy[10240];
__device__ float g_var2[10240];
__device__ float g_partial[BSZ];

// ---------------------------------------------------------------------------
// helpers
// ---------------------------------------------------------------------------
__device__ __forceinline__ float block_reduce_128(float v) {
    __shared__ float sh[4];
    #pragma unroll
    for (int o = 16; o; o >>= 1) v += __shfl_xor_sync(0xffffffffu, v, o);
    if ((threadIdx.x & 31) == 0) sh[threadIdx.x >> 5] = v;
    __syncthreads();
    if (threadIdx.x < 32) {
        v = (threadIdx.x < 4) ? sh[threadIdx.x] : 0.0f;
        v += __shfl_xor_sync(0xffffffffu, v, 2);
        v += __shfl_xor_sync(0xffffffffu, v, 1);
    }
    return v;  // valid in thread 0
}

__device__ __forceinline__ uint32_t smem_u32(const void* p) {
    return (uint32_t)__cvta_generic_to_shared(p);
}

__device__ __forceinline__ void cp16(uint32_t dst, const void* src, int src_sz) {
    asm volatile("cp.async.cg.shared.global [%0], [%1], 16, %2;\n"
                 :: "r"(dst), "l"(src), "r"(src_sz));
}

// ---------------------------------------------------------------------------
// XX[b] = sum_d feat[b][d]^2
// ---------------------------------------------------------------------------
__global__ void k_rownorm(const float* __restrict__ feat) {
    int b = blockIdx.x;
    const float4* row = (const float4*)(feat + (size_t)b * DD);
    float s = 0.0f;
    #pragma unroll
    for (int i = threadIdx.x; i < DD / 4; i += 128) {
        float4 v = row[i];
        s += v.x * v.x + v.y * v.y + v.z * v.z + v.w * v.w;
    }
    s = block_reduce_128(s);
    if (threadIdx.x == 0) g_xx[b] = s;
}

// ---------------------------------------------------------------------------
// YY[c] = sum_d means[c][d]^2 ; var2[c] = variance[c]^2
// ---------------------------------------------------------------------------
__global__ void k_colnorm(const float* __restrict__ means,
                          const float* __restrict__ variance) {
    int c = blockIdx.x;
    const float4* row = (const float4*)(means + (size_t)c * DD);
    float s = 0.0f;
    #pragma unroll
    for (int i = threadIdx.x; i < DD / 4; i += 128) {
        float4 v = row[i];
        s += v.x * v.x + v.y * v.y + v.z * v.z + v.w * v.w;
    }
    s = block_reduce_128(s);
    if (threadIdx.x == 0) {
        g_yy[c] = s;
        float v = variance[c];
        g_var2[c] = v * v;
    }
}

// ---------------------------------------------------------------------------
// copy means -> out
// ---------------------------------------------------------------------------
__global__ void k_copy(const float* __restrict__ means, float* __restrict__ dst) {
    size_t n = (size_t)CC * DD;
    for (size_t i = (size_t)blockIdx.x * blockDim.x + threadIdx.x; i < n;
         i += (size_t)gridDim.x * blockDim.x)
        dst[i] = means[i];
}

// ---------------------------------------------------------------------------
// per-row likelihood partials: g_partial[b] = ||feat[b] - means[labels[b]]||^2
// labels are INT32 (JAX default x64-disabled downgrades int64 -> int32)
// ---------------------------------------------------------------------------
__global__ void k_rowdiff(const float* __restrict__ feat,
                          const int* __restrict__ labels,
                          const float* __restrict__ means) {
    int b = blockIdx.x;
    int lbl = labels[b];
    if (lbl < 0) lbl = 0;
    if (lbl >= CC) lbl = CC - 1;
    const float4* f = (const float4*)(feat + (size_t)b * DD);
    const float4* m = (const float4*)(means + (size_t)lbl * DD);
    float s = 0.0f;
    #pragma unroll
    for (int i = threadIdx.x; i < DD / 4; i += 128) {
        float4 a = f[i], c = m[i];
        float dx = a.x - c.x, dy = a.y - c.y, dz = a.z - c.z, dw = a.w - c.w;
        s += dx * dx + dy * dy + dz * dz + dw * dw;
    }
    s = block_reduce_128(s);
    if (threadIdx.x == 0) g_partial[b] = s;
}

// deterministic final reduce
__global__ void k_reduce(float* __restrict__ out) {
    __shared__ float sh[1024];
    float s = 0.0f;
    for (int i = threadIdx.x; i < BSZ; i += 1024) s += g_partial[i];
    sh[threadIdx.x] = s;
    __syncthreads();
    for (int off = 512; off; off >>= 1) {
        if (threadIdx.x < off) sh[threadIdx.x] += sh[threadIdx.x + off];
        __syncthreads();
    }
    if (threadIdx.x == 0)
        out[0] = sh[0] * (0.01f * 0.5f / (float)BSZ);   // LAMBDA * 0.5 / B
}

// ---------------------------------------------------------------------------
// Main fused GEMM + epilogue.
// D[b][c] = -0.5*(XX[b] - 2*XY + YY[c]) * var2[c] * (1 + 0.1*[labels[b]==c])
// TF32 mma.sync m16n8k8, 128x128x16 tiles, 2-stage cp.async pipeline.
// ---------------------------------------------------------------------------
__global__ void __launch_bounds__(256, 2)
k_gemm(const float* __restrict__ feat, const float* __restrict__ means,
       const int* __restrict__ labels, float* __restrict__ out) {
    __shared__ __align__(16) float As[2][BM][BKP];
    __shared__ __align__(16) float Bs[2][BN][BKP];

    const int tid  = threadIdx.x;
    const int lane = tid & 31;
    const int warp = tid >> 5;
    const int g  = lane >> 2;
    const int tg = lane & 3;
    const int wr = warp & 3;
    const int wc = warp >> 2;

    const int bm0 = blockIdx.y * BM;
    const int bn0 = blockIdx.x * BN;

    const int ldrow = tid >> 2;
    const int ldcol = (tid & 3) * 4;
    const int brow0 = bn0 + ldrow;
    const int brow1 = bn0 + ldrow + 64;
    const float* aSrc0 = feat  + (size_t)(bm0 + ldrow)      * DD + ldcol;
    const float* aSrc1 = feat  + (size_t)(bm0 + ldrow + 64) * DD + ldcol;
    const float* bSrc0 = means + (size_t)(brow0 < CC ? brow0 : 0) * DD + ldcol;
    const float* bSrc1 = means + (size_t)(brow1 < CC ? brow1 : 0) * DD + ldcol;
    const int bsz0 = brow0 < CC ? 16 : 0;
    const int bsz1 = brow1 < CC ? 16 : 0;

    float acc[2][8][4];
    #pragma unroll
    for (int i = 0; i < 2; i++)
        #pragma unroll
        for (int j = 0; j < 8; j++)
            #pragma unroll
            for (int r = 0; r < 4; r++) acc[i][j][r] = 0.0f;

    const int NT = DD / BK;   // 64

    {
        cp16(smem_u32(&As[0][ldrow][ldcol]),      aSrc0, 16);
        cp16(smem_u32(&As[0][ldrow + 64][ldcol]), aSrc1, 16);
        cp16(smem_u32(&Bs[0][ldrow][ldcol]),      bSrc0, bsz0);
        cp16(smem_u32(&Bs[0][ldrow + 64][ldcol]), bSrc1, bsz1);
        asm volatile("cp.async.commit_group;\n");
    }

    for (int kt = 0; kt < NT; ++kt) {
        asm volatile("cp.async.wait_group 0;\n");
        __syncthreads();

        if (kt + 1 < NT) {
            int s2 = (kt + 1) & 1;
            int k0 = (kt + 1) * BK;
            cp16(smem_u32(&As[s2][ldrow][ldcol]),      aSrc0 + k0, 16);
            cp16(smem_u32(&As[s2][ldrow + 64][ldcol]), aSrc1 + k0, 16);
            cp16(smem_u32(&Bs[s2][ldrow][ldcol]),      bSrc0 + k0, bsz0);
            cp16(smem_u32(&Bs[s2][ldrow + 64][ldcol]), bSrc1 + k0, bsz1);
            asm volatile("cp.async.commit_group;\n");
        }

        const int s = kt & 1;
        #pragma unroll
        for (int ks = 0; ks < 2; ++ks) {
            const int kk = ks * 8;
            uint32_t af[2][4];
            uint32_t bf[8][2];
            #pragma unroll
            for (int i = 0; i < 2; i++) {
                int r = wr * 32 + i * 16 + g;
                af[i][0] = __float_as_uint(As[s][r][kk + tg]);
                af[i][1] = __float_as_uint(As[s][r + 8][kk + tg]);
                af[i][2] = __float_as_uint(As[s][r][kk + tg + 4]);
                af[i][3] = __float_as_uint(As[s][r + 8][kk + tg + 4]);
            }
            #pragma unroll
            for (int j = 0; j < 8; j++) {
                int r = wc * 64 + j * 8 + g;
                bf[j][0] = __float_as_uint(Bs[s][r][kk + tg]);
                bf[j][1] = __float_as_uint(Bs[s][r][kk + tg + 4]);
            }
            #pragma unroll
            for (int i = 0; i < 2; i++)
                #pragma unroll
                for (int j = 0; j < 8; j++) {
                    asm volatile(
                        "mma.sync.aligned.m16n8k8.row.col.f32.tf32.tf32.f32 "
                        "{%0,%1,%2,%3}, {%4,%5,%6,%7}, {%8,%9}, {%0,%1,%2,%3};\n"
                        : "+f"(acc[i][j][0]), "+f"(acc[i][j][1]),
                          "+f"(acc[i][j][2]), "+f"(acc[i][j][3])
                        : "r"(af[i][0]), "r"(af[i][1]), "r"(af[i][2]), "r"(af[i][3]),
                          "r"(bf[j][0]), "r"(bf[j][1]));
                }
        }
        __syncthreads();
    }

    // ---------------- fused epilogue ----------------
    const int rbase = bm0 + wr * 32;
    float xx[2][2];
    int lab[2][2];
    #pragma unroll
    for (int i = 0; i < 2; i++)
        #pragma unroll
        for (int h = 0; h < 2; h++) {
            int row = rbase + i * 16 + g + h * 8;
            xx[i][h]  = g_xx[row];
            lab[i][h] = labels[row];
        }

    const int cbase = bn0 + wc * 64;
    #pragma unroll
    for (int j = 0; j < 8; j++) {
        int c0 = cbase + j * 8 + tg * 2;
        if (c0 < CC) {
            float yy0 = g_yy[c0],  yy1 = g_yy[c0 + 1];
            float v0  = g_var2[c0], v1 = g_var2[c0 + 1];
            #pragma unroll
            for (int i = 0; i < 2; i++)
                #pragma unroll
                for (int h = 0; h < 2; h++) {
                    int row = rbase + i * 16 + g + h * 8;
                    float xy0 = acc[i][j][h * 2 + 0];
                    float xy1 = acc[i][j][h * 2 + 1];
                    float l0 = -0.5f * (xx[i][h] - 2.0f * xy0 + yy0) * v0;
                    float l1 = -0.5f * (xx[i][h] - 2.0f * xy1 + yy1) * v1;
                    if (lab[i][h] == c0)     l0 *= 1.1f;
                    if (lab[i][h] == c0 + 1) l1 *= 1.1f;
                    float2 st;
                    st.x = l0; st.y = l1;
                    *(float2*)(out + (size_t)row * CC + c0) = st;
                }
        }
    }
}

// ---------------------------------------------------------------------------
extern "C" void kernel_launch(void* const* d_in, const int* in_sizes, int n_in,
                              void* d_out, int out_size) {
    const float* feat     = (const float*)d_in[0];
    const int*   labels   = (const int*)d_in[1];     // int32 (JAX x64 disabled)
    const float* means    = (const float*)d_in[2];
    const float* variance = (const float*)d_in[3];
    float* out = (float*)d_out;

    const long long logitsN = (long long)BSZ * CC;      // 40,960,000
    const long long meansN  = (long long)CC * DD;       // 10,240,000

    k_rownorm<<<BSZ, 128>>>(feat);
    k_colnorm<<<CC, 128>>>(means, variance);

    dim3 grid((CC + BN - 1) / BN, BSZ / BM);   // 79 x 32
    k_gemm<<<grid, 256>>>(feat, means, labels, out);

    k_rowdiff<<<BSZ, 128>>>(feat, labels, means);

    long long osz = (long long)out_size;
    if (osz >= logitsN + 1 + meansN) {
        k_reduce<<<1, 1024>>>(out + logitsN);
        k_copy<<<2048, 256>>>(means, out + logitsN + 1);
    } else if (osz >= logitsN + 1) {
        k_reduce<<<1, 1024>>>(out + logitsN);
    }
}

// round 6
// speedup vs baseline: 1.9834x; 1.9834x over previous
#include <cuda_runtime.h>
#include <cuda_bf16.h>
#include <cstdint>

// Problem constants
#define BSZ 4096
#define DD  1024
#define CC  10000

// GEMM tiling (bf16 mma.sync m16n8k16, Ampere-style multistage)
#define BM 128
#define BN 128
#define BK 32
#define BKP 40                    // padded row: 40 bf16 = 80 bytes (conflict-free LDSM)
#define NSTG 4
#define NKT (DD / BK)             // 32
#define TSTRIDE (BM * BKP * 2)    // 10240 bytes per tile per stage
#define A_OFF(st) ((st) * TSTRIDE)
#define B_OFF(st) (NSTG * TSTRIDE + (st) * TSTRIDE)
#define SMEM_TOTAL (2 * NSTG * TSTRIDE)   // 81920

// Scratch (device globals -- no allocation allowed)
__device__ float g_xx[BSZ];
__device__ float g_yy[10240];
__device__ float g_var2[10240];
__device__ float g_partial[BSZ];
__device__ __align__(16) __nv_bfloat16 g_featb[(size_t)BSZ * DD];
__device__ __align__(16) __nv_bfloat16 g_meansb[(size_t)CC * DD];

// ---------------------------------------------------------------------------
// helpers
// ---------------------------------------------------------------------------
__device__ __forceinline__ float block_reduce_128(float v) {
    __shared__ float sh[4];
    #pragma unroll
    for (int o = 16; o; o >>= 1) v += __shfl_xor_sync(0xffffffffu, v, o);
    if ((threadIdx.x & 31) == 0) sh[threadIdx.x >> 5] = v;
    __syncthreads();
    if (threadIdx.x < 32) {
        v = (threadIdx.x < 4) ? sh[threadIdx.x] : 0.0f;
        v += __shfl_xor_sync(0xffffffffu, v, 2);
        v += __shfl_xor_sync(0xffffffffu, v, 1);
    }
    return v;  // valid in thread 0
}

__device__ __forceinline__ uint32_t smem_u32(const void* p) {
    return (uint32_t)__cvta_generic_to_shared(p);
}

__device__ __forceinline__ void cp16(uint32_t dst, const void* src, int src_sz) {
    asm volatile("cp.async.cg.shared.global [%0], [%1], 16, %2;\n"
                 :: "r"(dst), "l"(src), "r"(src_sz));
}

__device__ __forceinline__ void ldmx4(uint32_t* r, uint32_t addr) {
    asm volatile("ldmatrix.sync.aligned.m8n8.x4.shared.b16 {%0,%1,%2,%3}, [%4];"
                 : "=r"(r[0]), "=r"(r[1]), "=r"(r[2]), "=r"(r[3]) : "r"(addr));
}

// ---------------------------------------------------------------------------
// prep: feat -> bf16 copy + XX on ROUNDED values (consistency trick)
// ---------------------------------------------------------------------------
__global__ void k_prep_feat(const float* __restrict__ feat) {
    int b = blockIdx.x;
    const float4* row = (const float4*)(feat + (size_t)b * DD);
    uint2* dst = (uint2*)(g_featb + (size_t)b * DD);
    float s = 0.0f;
    for (int i = threadIdx.x; i < DD / 4; i += 128) {
        float4 v = row[i];
        __nv_bfloat162 p0 = __floats2bfloat162_rn(v.x, v.y);
        __nv_bfloat162 p1 = __floats2bfloat162_rn(v.z, v.w);
        uint2 u; u.x = *(uint32_t*)&p0; u.y = *(uint32_t*)&p1;
        dst[i] = u;
        float r0 = __bfloat162float(p0.x), r1 = __bfloat162float(p0.y);
        float r2 = __bfloat162float(p1.x), r3 = __bfloat162float(p1.y);
        s += r0 * r0 + r1 * r1 + r2 * r2 + r3 * r3;
    }
    s = block_reduce_128(s);
    if (threadIdx.x == 0) g_xx[b] = s;
}

__global__ void k_prep_means(const float* __restrict__ means,
                             const float* __restrict__ variance) {
    int c = blockIdx.x;
    const float4* row = (const float4*)(means + (size_t)c * DD);
    uint2* dst = (uint2*)(g_meansb + (size_t)c * DD);
    float s = 0.0f;
    for (int i = threadIdx.x; i < DD / 4; i += 128) {
        float4 v = row[i];
        __nv_bfloat162 p0 = __floats2bfloat162_rn(v.x, v.y);
        __nv_bfloat162 p1 = __floats2bfloat162_rn(v.z, v.w);
        uint2 u; u.x = *(uint32_t*)&p0; u.y = *(uint32_t*)&p1;
        dst[i] = u;
        float r0 = __bfloat162float(p0.x), r1 = __bfloat162float(p0.y);
        float r2 = __bfloat162float(p1.x), r3 = __bfloat162float(p1.y);
        s += r0 * r0 + r1 * r1 + r2 * r2 + r3 * r3;
    }
    s = block_reduce_128(s);
    if (threadIdx.x == 0) {
        g_yy[c] = s;
        float v = variance[c];
        g_var2[c] = v * v;
    }
}

// ---------------------------------------------------------------------------
// copy means -> out (exact fp32 passthrough)
// ---------------------------------------------------------------------------
__global__ void k_copy(const float* __restrict__ means, float* __restrict__ dst) {
    size_t n = (size_t)CC * DD;
    for (size_t i = (size_t)blockIdx.x * blockDim.x + threadIdx.x; i < n;
         i += (size_t)gridDim.x * blockDim.x)
        dst[i] = means[i];
}

// ---------------------------------------------------------------------------
// per-row likelihood partials (ORIGINAL fp32 data, int32 labels)
// ---------------------------------------------------------------------------
__global__ void k_rowdiff(const float* __restrict__ feat,
                          const int* __restrict__ labels,
                          const float* __restrict__ means) {
    int b = blockIdx.x;
    int lbl = labels[b];
    if (lbl < 0) lbl = 0;
    if (lbl >= CC) lbl = CC - 1;
    const float4* f = (const float4*)(feat + (size_t)b * DD);
    const float4* m = (const float4*)(means + (size_t)lbl * DD);
    float s = 0.0f;
    for (int i = threadIdx.x; i < DD / 4; i += 128) {
        float4 a = f[i], c = m[i];
        float dx = a.x - c.x, dy = a.y - c.y, dz = a.z - c.z, dw = a.w - c.w;
        s += dx * dx + dy * dy + dz * dz + dw * dw;
    }
    s = block_reduce_128(s);
    if (threadIdx.x == 0) g_partial[b] = s;
}

__global__ void k_reduce(float* __restrict__ out) {
    __shared__ float sh[1024];
    float s = 0.0f;
    for (int i = threadIdx.x; i < BSZ; i += 1024) s += g_partial[i];
    sh[threadIdx.x] = s;
    __syncthreads();
    for (int off = 512; off; off >>= 1) {
        if (threadIdx.x < off) sh[threadIdx.x] += sh[threadIdx.x + off];
        __syncthreads();
    }
    if (threadIdx.x == 0)
        out[0] = sh[0] * (0.01f * 0.5f / (float)BSZ);   // LAMBDA * 0.5 / B
}

// ---------------------------------------------------------------------------
// bf16 GEMM + fused epilogue.  128x128x32 tiles, 4-stage cp.async, ldmatrix,
// mma.sync.m16n8k16. Warp tile 64x32 (8 warps: 2x4).
// ---------------------------------------------------------------------------
__device__ __forceinline__ void load_tile(uint32_t aB, uint32_t bB,
                                          int bm0, int bn0, int k0, int tid) {
    const int c = tid & 3;          // 16B chunk within 64B row
    const int row = tid >> 2;       // 0..63
    cp16(aB + row * 80 + c * 16,
         g_featb + (size_t)(bm0 + row) * DD + k0 + c * 8, 16);
    cp16(aB + (row + 64) * 80 + c * 16,
         g_featb + (size_t)(bm0 + row + 64) * DD + k0 + c * 8, 16);
    const int br0 = bn0 + row, br1 = bn0 + row + 64;
    cp16(bB + row * 80 + c * 16,
         g_meansb + (size_t)(br0 < CC ? br0 : 0) * DD + k0 + c * 8,
         br0 < CC ? 16 : 0);
    cp16(bB + (row + 64) * 80 + c * 16,
         g_meansb + (size_t)(br1 < CC ? br1 : 0) * DD + k0 + c * 8,
         br1 < CC ? 16 : 0);
    asm volatile("cp.async.commit_group;\n" ::: "memory");
}

extern __shared__ char dsm[];

__global__ void __launch_bounds__(256, 2)
k_gemm(const int* __restrict__ labels, float* __restrict__ out) {
    const int tid  = threadIdx.x;
    const int lane = tid & 31;
    const int warp = tid >> 5;
    const int g  = lane >> 2;
    const int tg = lane & 3;
    const int wr = warp & 1;        // 2 warp-rows x 64
    const int wc = warp >> 1;       // 4 warp-cols x 32
    const int bm0 = blockIdx.y * BM;
    const int bn0 = blockIdx.x * BN;

    const uint32_t sb = smem_u32(dsm);

    // per-warp ldmatrix byte offsets within a tile
    // A (m16k16 frag): row = wr*64 + i*16 + (lane&15), kcol = kk + (lane>>4)*8
    const uint32_t aoff = (uint32_t)(wr * 64 + (lane & 15)) * 80 + (lane >> 4) * 16;
    // B (two n8k16 frags): n = wc*32 + jp*16 + (lane&7) + ((lane>>4)<<3),
    //                      kcol = kk + ((lane>>3)&1)*8
    const uint32_t boff = (uint32_t)(wc * 32 + (lane & 7) + ((lane >> 4) << 3)) * 80
                        + ((lane >> 3) & 1) * 16;

    float acc[4][4][4];
    #pragma unroll
    for (int i = 0; i < 4; i++)
        #pragma unroll
        for (int j = 0; j < 4; j++)
            #pragma unroll
            for (int r = 0; r < 4; r++) acc[i][j][r] = 0.0f;

    // prologue: stages 0..2
    load_tile(sb + A_OFF(0), sb + B_OFF(0), bm0, bn0, 0 * BK, tid);
    load_tile(sb + A_OFF(1), sb + B_OFF(1), bm0, bn0, 1 * BK, tid);
    load_tile(sb + A_OFF(2), sb + B_OFF(2), bm0, bn0, 2 * BK, tid);

    for (int kt = 0; kt < NKT; ++kt) {
        asm volatile("cp.async.wait_group 2;\n" ::: "memory");
        __syncthreads();

        const int kn = kt + 3;
        if (kn < NKT)
            load_tile(sb + A_OFF(kn & 3), sb + B_OFF(kn & 3), bm0, bn0, kn * BK, tid);
        else
            asm volatile("cp.async.commit_group;\n" ::: "memory");

        const uint32_t aT = sb + A_OFF(kt & 3) + aoff;
        const uint32_t bT = sb + B_OFF(kt & 3) + boff;

        #pragma unroll
        for (int ks = 0; ks < 2; ++ks) {
            uint32_t af[4][4], bf[2][4];
            #pragma unroll
            for (int i = 0; i < 4; i++)
                ldmx4(af[i], aT + i * (16 * 80) + ks * 32);
            #pragma unroll
            for (int jp = 0; jp < 2; jp++)
                ldmx4(bf[jp], bT + jp * (16 * 80) + ks * 32);

            #pragma unroll
            for (int i = 0; i < 4; i++)
                #pragma unroll
                for (int j = 0; j < 4; j++) {
                    const uint32_t b0 = bf[j >> 1][(j & 1) * 2 + 0];
                    const uint32_t b1 = bf[j >> 1][(j & 1) * 2 + 1];
                    asm volatile(
                        "mma.sync.aligned.m16n8k16.row.col.f32.bf16.bf16.f32 "
                        "{%0,%1,%2,%3}, {%4,%5,%6,%7}, {%8,%9}, {%0,%1,%2,%3};\n"
                        : "+f"(acc[i][j][0]), "+f"(acc[i][j][1]),
                          "+f"(acc[i][j][2]), "+f"(acc[i][j][3])
                        : "r"(af[i][0]), "r"(af[i][1]), "r"(af[i][2]), "r"(af[i][3]),
                          "r"(b0), "r"(b1));
                }
        }
    }

    // ---------------- fused epilogue ----------------
    const int rbase = bm0 + wr * 64;
    float xx[4][2];
    int lab[4][2];
    #pragma unroll
    for (int i = 0; i < 4; i++)
        #pragma unroll
        for (int h = 0; h < 2; h++) {
            int row = rbase + i * 16 + g + h * 8;
            xx[i][h]  = g_xx[row];
            lab[i][h] = labels[row];
        }

    const int cbase = bn0 + wc * 32;
    #pragma unroll
    for (int j = 0; j < 4; j++) {
        int c0 = cbase + j * 8 + tg * 2;
        if (c0 < CC) {
            float yy0 = g_yy[c0],   yy1 = g_yy[c0 + 1];
            float v0  = g_var2[c0], v1  = g_var2[c0 + 1];
            #pragma unroll
            for (int i = 0; i < 4; i++)
                #pragma unroll
                for (int h = 0; h < 2; h++) {
                    int row = rbase + i * 16 + g + h * 8;
                    float xy0 = acc[i][j][h * 2 + 0];
                    float xy1 = acc[i][j][h * 2 + 1];
                    float l0 = -0.5f * (xx[i][h] - 2.0f * xy0 + yy0) * v0;
                    float l1 = -0.5f * (xx[i][h] - 2.0f * xy1 + yy1) * v1;
                    if (lab[i][h] == c0)     l0 *= 1.1f;
                    if (lab[i][h] == c0 + 1) l1 *= 1.1f;
                    float2 st; st.x = l0; st.y = l1;
                    *(float2*)(out + (size_t)row * CC + c0) = st;
                }
        }
    }
}

// ---------------------------------------------------------------------------
extern "C" void kernel_launch(void* const* d_in, const int* in_sizes, int n_in,
                              void* d_out, int out_size) {
    const float* feat     = (const float*)d_in[0];
    const int*   labels   = (const int*)d_in[1];     // int32 (JAX x64 disabled)
    const float* means    = (const float*)d_in[2];
    const float* variance = (const float*)d_in[3];
    float* out = (float*)d_out;

    const long long logitsN = (long long)BSZ * CC;      // 40,960,000
    const long long meansN  = (long long)CC * DD;       // 10,240,000

    cudaFuncSetAttribute(k_gemm, cudaFuncAttributeMaxDynamicSharedMemorySize,
                         SMEM_TOTAL);

    k_prep_feat<<<BSZ, 128>>>(feat);
    k_prep_means<<<CC, 128>>>(means, variance);

    dim3 grid((CC + BN - 1) / BN, BSZ / BM);   // 79 x 32
    k_gemm<<<grid, 256, SMEM_TOTAL>>>(labels, out);

    k_rowdiff<<<BSZ, 128>>>(feat, labels, means);

    long long osz = (long long)out_size;
    if (osz >= logitsN + 1 + meansN) {
        k_reduce<<<1, 1024>>>(out + logitsN);
        k_copy<<<2048, 256>>>(means, out + logitsN + 1);
    } else if (osz >= logitsN + 1) {
        k_reduce<<<1, 1024>>>(out + logitsN);
    }
}